// round 15
// baseline (speedup 1.0000x reference)
#include <cuda_runtime.h>
#include <cuda_bf16.h>
#include <math.h>
#include <cstdint>

#define Bb   16
#define L    4096
#define D    512
#define S    64
#define BL   (Bb*L)      // 65536
#define NCAT 256         // 4 groups of 64: [dt, B, C, xproj]

// ---------------- scratch (device globals) --------------------------------
__device__ float          g_c0[NCAT];
__device__ float          g_c1[NCAT];
__device__ float          g_A[S];
__device__ float          g_Ds[D];
__device__ int            g_DsNZ;          // 1 if any clip(Dp) != 0
__device__ __nv_bfloat16  g_Whi[NCAT*D];
__device__ __nv_bfloat16  g_Wlo[NCAT*D];
__device__ __nv_bfloat16  g_Wouthi[D*S];
__device__ __nv_bfloat16  g_Woutlo[D*S];
__device__ float          g_Ac[Bb*S*L];
__device__ float          g_BX[Bb*S*L];
__device__ float          g_Cc[Bb*S*L];
// ys in s-pair-interleaved words: [b][sp=s/2][l]
__device__ uint32_t       g_ys2h[Bb*(S/2)*L];
__device__ uint32_t       g_ys2l[Bb*(S/2)*L];

// ---------------- helpers (all plain sm_80+ PTX) --------------------------
__device__ __forceinline__ uint32_t smem_u32(const void* p) {
    uint32_t a;
    asm("{ .reg .u64 t; cvta.to.shared.u64 t, %1; cvt.u32.u64 %0, t; }"
        : "=r"(a) : "l"(p));
    return a;
}
__device__ __forceinline__ void mma_bf16(float* c, const uint32_t* a, const uint32_t* b) {
    asm volatile(
        "mma.sync.aligned.m16n8k16.row.col.f32.bf16.bf16.f32 "
        "{%0,%1,%2,%3}, {%4,%5,%6,%7}, {%8,%9}, {%0,%1,%2,%3};"
        : "+f"(c[0]), "+f"(c[1]), "+f"(c[2]), "+f"(c[3])
        : "r"(a[0]), "r"(a[1]), "r"(a[2]), "r"(a[3]), "r"(b[0]), "r"(b[1]));
}
__device__ __forceinline__ void cp16(uint32_t saddr, const void* g) {
    asm volatile("cp.async.cg.shared.global [%0], [%1], 16;" :: "r"(saddr), "l"(g));
}
#define CP_COMMIT() asm volatile("cp.async.commit_group;")
#define CP_WAIT0()  asm volatile("cp.async.wait_group 0;" ::: "memory")
#define CP_WAIT1()  asm volatile("cp.async.wait_group 1;" ::: "memory")

__device__ __forceinline__ uint32_t pkbf(__nv_bfloat16 a, __nv_bfloat16 b) {
    __nv_bfloat162 t(a, b);
    return *reinterpret_cast<uint32_t*>(&t);
}

// ---------------- K0: weight prep (fold ln_w, bf16 split, PERMUTED) -------
__global__ void k0_prep(const float* __restrict__ Wx, const float* __restrict__ bx,
                        const float* __restrict__ Wdt, const float* __restrict__ bdt,
                        const float* __restrict__ WB, const float* __restrict__ WC,
                        const float* __restrict__ A_log, const float* __restrict__ Dp,
                        const float* __restrict__ ln_w, const float* __restrict__ ln_b) {
    int scat = blockIdx.x;            // 0..255 = output row n
    int g = scat >> 6, s = scat & 63;
    const float* W = (g == 0) ? Wdt : (g == 1) ? WB : (g == 2) ? WC : Wx;
    float bias = (g == 0) ? bdt[s] : (g == 3) ? bx[s] : 0.f;
    int tid = threadIdx.x;            // 128
    int n = scat;
    float c1p = 0.f, c0p = 0.f;
    for (int dp = tid; dp < D/2; dp += 128) {
        int d0 = dp * 2;
        float w0 = W[s*D + d0],     w1 = W[s*D + d0 + 1];
        float wp0 = w0 * ln_w[d0],  wp1 = w1 * ln_w[d0 + 1];
        __nv_bfloat16 h0 = __float2bfloat16_rn(wp0);
        __nv_bfloat16 h1 = __float2bfloat16_rn(wp1);
        __nv_bfloat16 l0 = __float2bfloat16_rn(wp0 - __bfloat162float(h0));
        __nv_bfloat16 l1 = __float2bfloat16_rn(wp1 - __bfloat162float(h1));
        int chunk = d0 >> 4, wc = (d0 & 15) >> 1;
        size_t off = (size_t)chunk*8192 + (size_t)(n >> 3)*256
                   + (size_t)((n & 7)*4 + (wc & 3))*8 + (size_t)(wc >> 2)*4;
        *(uint32_t*)((char*)g_Whi + off) = pkbf(h0, h1);
        *(uint32_t*)((char*)g_Wlo + off) = pkbf(l0, l1);
        c1p += wp0 + wp1;
        c0p += w0 * ln_b[d0] + w1 * ln_b[d0 + 1];
    }
    __shared__ float r1[128], r0[128];
    r1[tid] = c1p; r0[tid] = c0p; __syncthreads();
    for (int o = 64; o > 0; o >>= 1) {
        if (tid < o) { r1[tid] += r1[tid+o]; r0[tid] += r0[tid+o]; }
        __syncthreads();
    }
    if (tid == 0) { g_c1[scat] = r1[0]; g_c0[scat] = r0[0] + bias; }
    if (scat == 0 && tid < S) g_A[tid] = -expf(A_log[tid]);
    if (scat == 1) {
        int nz = 0;
        for (int d = tid; d < D; d += 128) {
            float ds = fminf(fmaxf(Dp[d], -2.f), 2.f);
            g_Ds[d] = ds;
            if (ds != 0.f) nz = 1;
        }
        __shared__ int anynz[128];
        anynz[tid] = nz; __syncthreads();
        for (int o = 64; o > 0; o >>= 1) {
            if (tid < o) anynz[tid] |= anynz[tid + o];
            __syncthreads();
        }
        if (tid == 0) g_DsNZ = anynz[0];
    }
}

// ---------------- K0b: Wout bf16 split ------------------------------------
__global__ void k0b_prep(const float* __restrict__ Wout) {
    int i = blockIdx.x * 256 + threadIdx.x;   // D*S = 32768
    float w = Wout[i];
    __nv_bfloat16 hi = __float2bfloat16_rn(w);
    g_Wouthi[i] = hi;
    g_Woutlo[i] = __float2bfloat16_rn(w - __bfloat162float(hi));
}

// ---------------- K2: HMMA bf16-split LN + projection + SSM epilogue ------
// K-chunk 32 (16 iterations). A double-buffered (sync-ordered),
// B in a 3-deep cp.async ring with wait-depth 1.
#define OFF_STATS 0
#define OFF_C1    1024
#define OFF_C0    2048
#define OFF_SA    3072
#define K2_ABUF0  3584
#define K2_ABSZ   16384        // AH (2x4096) | AL (2x4096)
#define K2_BBUF0  (K2_ABUF0 + 2*K2_ABSZ)   // 36352
#define K2_BBSZ   32768        // BH (2x8192) | BL (2x8192)
#define OFF_V     3584
#define VSTRIDE   136
#define K2_SMEM   (OFF_V + 256*VSTRIDE*4)   // 142848

__global__ void __launch_bounds__(512, 1) k2_mma(const float* __restrict__ x) {
    extern __shared__ __align__(16) char sm[];
    const uint32_t sb = smem_u32(sm);
    const int tid = threadIdx.x, lane = tid & 31, w = tid >> 5;   // w: 0..15
    const int row0 = blockIdx.x * 128;

    if (tid < 256) {
        ((float*)(sm + OFF_C1))[tid] = g_c1[tid];
        ((float*)(sm + OFF_C0))[tid] = g_c0[tid];
    }
    if (tid < 64) ((float*)(sm + OFF_SA))[tid] = g_A[tid];

    const int m0 = 64 * (w & 1);
    const int n0 = 32 * (w >> 1);
    const int mt0 = m0 >> 4;
    const int nb0 = n0 >> 3;

    float acc[4][4][4];
#pragma unroll
    for (int a = 0; a < 4; a++)
#pragma unroll
        for (int b = 0; b < 4; b++)
#pragma unroll
            for (int c = 0; c < 4; c++) acc[a][b][c] = 0.f;

    float xs = 0.f, xss = 0.f;
    float4 ax[2];
    auto loadA = [&](int ks) {
        int r = tid >> 2, q4 = tid & 3;
#pragma unroll
        for (int h = 0; h < 2; h++)
            ax[h] = *(const float4*)(x + (size_t)(row0 + r)*D + ks*32 + h*16 + q4*4);
    };
    auto storeA = [&](int abufo) {
        int r = tid >> 2, q4 = tid & 3;
        int mt = r >> 4, rr = r & 15;
#pragma unroll
        for (int h = 0; h < 2; h++) {
            float v[4] = {ax[h].x, ax[h].y, ax[h].z, ax[h].w};
            xs  += v[0] + v[1] + v[2] + v[3];
            xss += v[0]*v[0] + v[1]*v[1] + v[2]*v[2] + v[3]*v[3];
            __nv_bfloat16 hh[4], ll[4];
#pragma unroll
            for (int e = 0; e < 4; e++) {
                hh[e] = __float2bfloat16_rn(v[e]);
                ll[e] = __float2bfloat16_rn(v[e] - __bfloat162float(hh[e]));
            }
            uint32_t wH[2] = {pkbf(hh[0], hh[1]), pkbf(hh[2], hh[3])};
            uint32_t wL[2] = {pkbf(ll[0], ll[1]), pkbf(ll[2], ll[3])};
#pragma unroll
            for (int j = 0; j < 2; j++) {
                int wc = 2*q4 + j;
                int base = abufo + h*4096 + mt*512 + ((rr & 7)*4 + (wc & 3))*16
                         + ((rr >> 3) + ((wc >> 2) << 1))*4;
                *(uint32_t*)(sm + base)         = wH[j];
                *(uint32_t*)(sm + base + 8192)  = wL[j];
            }
        }
    };
    auto cpB = [&](int ks, int bbufo) {
#pragma unroll
        for (int h = 0; h < 2; h++) {
            const char* gh = (const char*)g_Whi + (size_t)(ks*2 + h)*8192 + tid*16;
            const char* gl = (const char*)g_Wlo + (size_t)(ks*2 + h)*8192 + tid*16;
            cp16(sb + bbufo + h*8192 + tid*16, gh);
            cp16(sb + bbufo + 16384 + h*8192 + tid*16, gl);
        }
    };
    auto compute = [&](int abufo, int bbufo, int h) {
        uint32_t bH[4][2], bL[4][2];
#pragma unroll
        for (int nt = 0; nt < 4; nt++) {
            int boff = bbufo + h*8192 + (nb0 + nt)*256 + lane*8;
            uint2 th = *(const uint2*)(sm + boff);
            uint2 tl = *(const uint2*)(sm + boff + 16384);
            bH[nt][0] = th.x; bH[nt][1] = th.y;
            bL[nt][0] = tl.x; bL[nt][1] = tl.y;
        }
#pragma unroll
        for (int mt = 0; mt < 4; mt++) {
            int aoff = abufo + h*4096 + (mt0 + mt)*512 + lane*16;
            uint4 tH = *(const uint4*)(sm + aoff);
            uint4 tL = *(const uint4*)(sm + aoff + 8192);
            uint32_t aH[4] = {tH.x, tH.y, tH.z, tH.w};
            uint32_t aL[4] = {tL.x, tL.y, tL.z, tL.w};
#pragma unroll
            for (int nt = 0; nt < 4; nt++) mma_bf16(acc[mt][nt], aH, bH[nt]);
#pragma unroll
            for (int nt = 0; nt < 4; nt++) mma_bf16(acc[mt][nt], aL, bH[nt]);
#pragma unroll
            for (int nt = 0; nt < 4; nt++) mma_bf16(acc[mt][nt], aH, bL[nt]);
        }
    };

    // prologue: B groups 0 and 1 in flight; A chunk 0 staged.
    loadA(0);
    cpB(0, K2_BBUF0);                 CP_COMMIT();
    cpB(1, K2_BBUF0 + K2_BBSZ);       CP_COMMIT();
    storeA(K2_ABUF0);

    for (int s = 0; s < 16; s++) {
        int ab = K2_ABUF0 + (s & 1) * K2_ABSZ;
        int bbp = K2_BBUF0 + (s % 3) * K2_BBSZ;
        if (s == 15) CP_WAIT0(); else CP_WAIT1();   // B chunk s landed
        __syncthreads();                            // A(s) + B(s) visible; buffers free
        if (s < 14) { cpB(s + 2, K2_BBUF0 + ((s + 2) % 3) * K2_BBSZ); CP_COMMIT(); }
        if (s < 15) loadA(s + 1);
        compute(ab, bbp, 0);
        compute(ab, bbp, 1);
        if (s < 15) storeA(K2_ABUF0 + ((s + 1) & 1) * K2_ABSZ);
    }

    // ---- fused LN stats: quad reduction ----
    xs  += __shfl_xor_sync(0xffffffffu, xs, 1);
    xs  += __shfl_xor_sync(0xffffffffu, xs, 2);
    xss += __shfl_xor_sync(0xffffffffu, xss, 1);
    xss += __shfl_xor_sync(0xffffffffu, xss, 2);
    __syncthreads();                  // all compute reads done before V overlay
    if ((tid & 3) == 0) {
        int r = tid >> 2;
        float mu  = xs * (1.f / D);
        float var = xss * (1.f / D) - mu * mu;
        *(float2*)(sm + OFF_STATS + r*8) = make_float2(mu, rsqrtf(var + 1e-5f));
    }
    __syncthreads();

    // ---- phase 1: LN-fold, scatter v into SMEM V[col][row] ----
    float* V = (float*)(sm + OFF_V);
#pragma unroll
    for (int mt = 0; mt < 4; mt++) {
        int r_ = m0 + mt*16 + (lane >> 2);
        float2 st0 = *(const float2*)(sm + OFF_STATS + r_*8);
        float2 st1 = *(const float2*)(sm + OFF_STATS + (r_+8)*8);
#pragma unroll
        for (int nt = 0; nt < 4; nt++) {
            int c_ = n0 + nt*8 + 2*(lane & 3);
            float c1a = ((const float*)(sm + OFF_C1))[c_];
            float c1b = ((const float*)(sm + OFF_C1))[c_ + 1];
            float c0a = ((const float*)(sm + OFF_C0))[c_];
            float c0b = ((const float*)(sm + OFF_C0))[c_ + 1];
            V[c_*VSTRIDE + r_]         = st0.y*(acc[mt][nt][0] - st0.x*c1a) + c0a;
            V[(c_+1)*VSTRIDE + r_]     = st0.y*(acc[mt][nt][1] - st0.x*c1b) + c0b;
            V[c_*VSTRIDE + r_ + 8]     = st1.y*(acc[mt][nt][2] - st1.x*c1a) + c0a;
            V[(c_+1)*VSTRIDE + r_ + 8] = st1.y*(acc[mt][nt][3] - st1.x*c1b) + c0b;
        }
    }
    __syncthreads();

    // ---- phase 2: softplus/exp math, write (B,S,L) scan operands ----
    int s_ = tid & 63, rb = tid >> 6;
    float Aval = ((const float*)(sm + OFF_SA))[s_];
    int bidx = row0 >> 12;
    int l0 = row0 & (L - 1);
    size_t ob = ((size_t)(bidx*S + s_))*L + l0 + rb*16;
#pragma unroll
    for (int t4 = 0; t4 < 4; t4++) {
        int row = rb*16 + t4*4;
        float4 v0 = *(const float4*)(V + (0*64 + s_)*VSTRIDE + row);
        float4 v1 = *(const float4*)(V + (1*64 + s_)*VSTRIDE + row);
        float4 v2 = *(const float4*)(V + (2*64 + s_)*VSTRIDE + row);
        float4 v3 = *(const float4*)(V + (3*64 + s_)*VSTRIDE + row);
        float oa[4], obx[4], oc[4];
        float z0[4] = {v0.x, v0.y, v0.z, v0.w};
        float zb[4] = {v1.x, v1.y, v1.z, v1.w};
        float zc[4] = {v2.x, v2.y, v2.z, v2.w};
        float zx[4] = {v3.x, v3.y, v3.z, v3.w};
#pragma unroll
        for (int e = 0; e < 4; e++) {
            float z = z0[e];
            float sp = fmaxf(z, 0.f) + log1pf(expf(-fabsf(z)));
            float delta = sp * 0.01f + 1e-4f;
            float dA = fminf(fmaxf(delta * Aval, -10.f), -1e-4f);
            float ad = expf(dA);
            oa[e]  = fminf(fmaxf(ad, 0.001f), 0.999f) + 1e-10f;
            obx[e] = delta * zb[e] * zx[e];
            oc[e]  = zc[e];
        }
        *(float4*)(g_Ac + ob + t4*4) = make_float4(oa[0], oa[1], oa[2], oa[3]);
        *(float4*)(g_BX + ob + t4*4) = make_float4(obx[0], obx[1], obx[2], obx[3]);
        *(float4*)(g_Cc + ob + t4*4) = make_float4(oc[0], oc[1], oc[2], oc[3]);
    }
}

// ---------------- K3: affine scan; SMEM-staged coalesced streams ----------
#define K3_HALF 20480
#define K3_SA   0
#define K3_SB   (2*K3_HALF)
#define K3_SC   (4*K3_HALF)
#define K3_SMEM (6*K3_HALF)           // 122880
__global__ void __launch_bounds__(512, 1) k3_scan() {
    extern __shared__ __align__(16) char sm[];
    const uint32_t sb = smem_u32(sm);
    int tid = threadIdx.x;
    int h = tid >> 8, t = tid & 255;
    int lane = tid & 31, w = tid >> 5;
    int b = blockIdx.x >> 5, sp = blockIdx.x & 31;

#pragma unroll
    for (int i = 0; i < 4; i++) {
        int c = tid + 512*i;
        int h2 = c >> 10, cc = c & 1023;
        int s2 = sp*2 + h2;
        size_t gbase = ((size_t)(b*S + s2))*L + cc*4;
        uint32_t dst = h2*K3_HALF + (cc >> 2)*80 + (cc & 3)*16;
        cp16(sb + K3_SA + dst, g_Ac + gbase);
        cp16(sb + K3_SB + dst, g_BX + gbase);
        cp16(sb + K3_SC + dst, g_Cc + gbase);
    }
    CP_COMMIT(); CP_WAIT0();
    __syncthreads();

    const char* gbase_ = sm + h*K3_HALF + t*80;
    float a[16], bxv[16];
#pragma unroll
    for (int q = 0; q < 4; q++) {
        *(float4*)(a + q*4)   = *(const float4*)(gbase_ + K3_SA + q*16);
        *(float4*)(bxv + q*4) = *(const float4*)(gbase_ + K3_SB + q*16);
    }

    float P = 1.f, Q = 0.f;
#pragma unroll
    for (int i = 0; i < 16; i++) { Q = a[i] * (Q + bxv[i]); P *= a[i]; }

#pragma unroll
    for (int d = 1; d < 32; d <<= 1) {
        float Pp = __shfl_up_sync(0xffffffffu, P, d);
        float Qp = __shfl_up_sync(0xffffffffu, Q, d);
        if (lane >= d) { Q = P * Qp + Q; P = P * Pp; }
    }
    __shared__ float wP[16], wQ[16];
    if (lane == 31) { wP[w] = P; wQ[w] = Q; }
    __syncthreads();
    float Qw = 0.f;
    for (int w_ = h*8; w_ < w; w_++) { Qw = wP[w_] * Qw + wQ[w_]; }
    float P2 = __shfl_up_sync(0xffffffffu, P, 1);
    float Q2 = __shfl_up_sync(0xffffffffu, Q, 1);
    float hh = (lane == 0) ? Qw : (P2 * Qw + Q2);

    float y[16];
#pragma unroll
    for (int q = 0; q < 4; q++) {
        float4 cv = *(const float4*)(gbase_ + K3_SC + q*16);
        float c4[4] = {cv.x, cv.y, cv.z, cv.w};
#pragma unroll
        for (int e = 0; e < 4; e++) {
            int i = q*4 + e;
            hh = a[i] * (hh + bxv[i]);
            y[i] = c4[e] * hh;
        }
    }

    float* sy = (float*)(sm + K3_SA);
    __syncthreads();
    if (h == 1) {
#pragma unroll
        for (int i = 0; i < 16; i++) sy[t*17 + i] = y[i];
    }
    __syncthreads();
    if (h == 0) {
        uint32_t whi[16], wlo[16];
#pragma unroll
        for (int i = 0; i < 16; i++) {
            float ye = y[i];
            float yo = sy[t*17 + i];
            __nv_bfloat16 he = __float2bfloat16_rn(ye);
            __nv_bfloat16 ho = __float2bfloat16_rn(yo);
            __nv_bfloat16 le = __float2bfloat16_rn(ye - __bfloat162float(he));
            __nv_bfloat16 lo = __float2bfloat16_rn(yo - __bfloat162float(ho));
            whi[i] = pkbf(he, ho);
            wlo[i] = pkbf(le, lo);
        }
        size_t off = ((size_t)(b*32 + sp))*L + t*16;
#pragma unroll
        for (int q = 0; q < 4; q++) {
            *(uint4*)(g_ys2h + off + q*4) = make_uint4(whi[q*4], whi[q*4+1], whi[q*4+2], whi[q*4+3]);
            *(uint4*)(g_ys2l + off + q*4) = make_uint4(wlo[q*4], wlo[q*4+1], wlo[q*4+2], wlo[q*4+3]);
        }
    }
}

// ---------------- K4: out = ys @ Wout^T + bout [+ clip(Dp)*x] (HMMA) ------
#define K4_AH   0
#define K4_AL   9216
#define K4_B0   18432
#define K4_B1   55296
#define K4_BLO  18432
#define K4_SMEM 92160
__global__ void __launch_bounds__(256, 2) k4_mma(const float* __restrict__ x,
                                                 const float* __restrict__ bout,
                                                 float* __restrict__ out) {
    extern __shared__ __align__(16) char sm[];
    const uint32_t sb = smem_u32(sm);
    const int tid = threadIdx.x, lane = tid & 31, w = tid >> 5;
    const int row0 = blockIdx.x * 64;
    const int bidx = row0 >> 12;
    const int l0   = row0 & (L - 1);
    const int dsnz = g_DsNZ;

    auto cpB = [&](int d0, uint32_t bufo) {
#pragma unroll
        for (int i = 0; i < 4; i++) {
            int li = tid*4 + i;
            int n = li >> 3, q = li & 7;
            uint32_t dst = bufo + n*144 + q*16;
            cp16(sb + dst,          g_Wouthi + (size_t)(d0 + n)*S + q*8);
            cp16(sb + dst + K4_BLO, g_Woutlo + (size_t)(d0 + n)*S + q*8);
        }
    };

#pragma unroll
    for (int i = 0; i < 2; i++) {
        int chunk = tid + 256*i;
        int sp = chunk >> 4, lq = chunk & 15;
        size_t g = ((size_t)(bidx*32 + sp))*L + l0 + lq*4;
        uint32_t dsto = (uint32_t)(sp*72 + lq*4) * 4u;
        cp16(sb + K4_AH + dsto, g_ys2h + g);
        cp16(sb + K4_AL + dsto, g_ys2l + g);
    }
    cpB(0, K4_B0);
    CP_COMMIT();
    CP_WAIT0();
    __syncthreads();

    const int m0 = 32 * (w & 1);
    const int n0 = 32 * (w >> 1);

    for (int dt = 0; dt < 4; dt++) {
        uint32_t bufo = (dt & 1) ? K4_B1 : K4_B0;
        if (dt < 3) { cpB((dt + 1) * 128, (dt & 1) ? K4_B0 : K4_B1); CP_COMMIT(); }
        int d0 = dt * 128;

        float acc[2][4][4];
#pragma unroll
        for (int a = 0; a < 2; a++)
#pragma unroll
            for (int b = 0; b < 4; b++)
#pragma unroll
                for (int c = 0; c < 4; c++) acc[a][b][c] = 0.f;

#pragma unroll
        for (int kk = 0; kk < 4; kk++) {
            int kp = kk*16 + 2*(lane & 3);
            uint32_t bH[4][2], bL[4][2];
#pragma unroll
            for (int nt = 0; nt < 4; nt++) {
                uint32_t boff = bufo + (n0 + nt*8 + (lane >> 2))*144 + kp*2;
                bH[nt][0] = *(const uint32_t*)(sm + boff);
                bH[nt][1] = *(const uint32_t*)(sm + boff + 16);
                bL[nt][0] = *(const uint32_t*)(sm + boff + K4_BLO);
                bL[nt][1] = *(const uint32_t*)(sm + boff + K4_BLO + 16);
            }
#pragma unroll
            for (int mt = 0; mt < 2; mt++) {
                int abase = ((kk*8 + (lane & 3))*72 + m0 + mt*16 + (lane >> 2)) * 4;
                uint32_t aH[4], aL[4];
                aH[0] = *(const uint32_t*)(sm + K4_AH + abase);
                aH[1] = *(const uint32_t*)(sm + K4_AH + abase + 32);       // l+8
                aH[2] = *(const uint32_t*)(sm + K4_AH + abase + 4*72*4);   // sp+4
                aH[3] = *(const uint32_t*)(sm + K4_AH + abase + 4*72*4 + 32);
                aL[0] = *(const uint32_t*)(sm + K4_AL + abase);
                aL[1] = *(const uint32_t*)(sm + K4_AL + abase + 32);
                aL[2] = *(const uint32_t*)(sm + K4_AL + abase + 4*72*4);
                aL[3] = *(const uint32_t*)(sm + K4_AL + abase + 4*72*4 + 32);
#pragma unroll
                for (int nt = 0; nt < 4; nt++) mma_bf16(acc[mt][nt], aH, bH[nt]);
#pragma unroll
                for (int nt = 0; nt < 4; nt++) mma_bf16(acc[mt][nt], aL, bH[nt]);
#pragma unroll
                for (int nt = 0; nt < 4; nt++) mma_bf16(acc[mt][nt], aH, bL[nt]);
            }
        }

        if (dsnz) {
#pragma unroll
            for (int nt = 0; nt < 4; nt++) {
                int cd = d0 + n0 + nt*8 + 2*(lane & 3);
                float2 bo = *(const float2*)(bout + cd);
                float2 ds = *(const float2*)(g_Ds + cd);
#pragma unroll
                for (int mt = 0; mt < 2; mt++) {
                    int r_ = row0 + m0 + mt*16 + (lane >> 2);
                    float2 xv0 = *(const float2*)(x + (size_t)r_*D + cd);
                    float2 xv1 = *(const float2*)(x + (size_t)(r_+8)*D + cd);
                    float2 o0, o1;
                    o0.x = acc[mt][nt][0] + bo.x + ds.x*xv0.x;
                    o0.y = acc[mt][nt][1] + bo.y + ds.y*xv0.y;
                    o1.x = acc[mt][nt][2] + bo.x + ds.x*xv1.x;
                    o1.y = acc[mt][nt][3] + bo.y + ds.y*xv1.y;
                    *(float2*)(out + (size_t)r_*D + cd)     = o0;
                    *(float2*)(out + (size_t)(r_+8)*D + cd) = o1;
                }
            }
        } else {
#pragma unroll
            for (int nt = 0; nt < 4; nt++) {
                int cd = d0 + n0 + nt*8 + 2*(lane & 3);
                float2 bo = *(const float2*)(bout + cd);
#pragma unroll
                for (int mt = 0; mt < 2; mt++) {
                    int r_ = row0 + m0 + mt*16 + (lane >> 2);
                    float2 o0, o1;
                    o0.x = acc[mt][nt][0] + bo.x;
                    o0.y = acc[mt][nt][1] + bo.y;
                    o1.x = acc[mt][nt][2] + bo.x;
                    o1.y = acc[mt][nt][3] + bo.y;
                    *(float2*)(out + (size_t)r_*D + cd)     = o0;
                    *(float2*)(out + (size_t)(r_+8)*D + cd) = o1;
                }
            }
        }

        if (dt < 3) CP_WAIT0();
        __syncthreads();
    }
}

// ---------------- launch --------------------------------------------------
extern "C" void kernel_launch(void* const* d_in, const int* in_sizes, int n_in,
                              void* d_out, int out_size) {
    const float* x     = (const float*)d_in[0];
    const float* ln_w  = (const float*)d_in[1];
    const float* ln_b  = (const float*)d_in[2];
    const float* Wx    = (const float*)d_in[3];
    const float* bx    = (const float*)d_in[4];
    const float* Wdt   = (const float*)d_in[5];
    const float* bdt   = (const float*)d_in[6];
    const float* A_log = (const float*)d_in[7];
    const float* WB    = (const float*)d_in[8];
    const float* WC    = (const float*)d_in[9];
    const float* Dp    = (const float*)d_in[10];
    const float* Wout  = (const float*)d_in[11];
    const float* bout  = (const float*)d_in[12];
    float* out = (float*)d_out;

    cudaFuncSetAttribute(k2_mma, cudaFuncAttributeMaxDynamicSharedMemorySize, K2_SMEM);
    cudaFuncSetAttribute(k3_scan, cudaFuncAttributeMaxDynamicSharedMemorySize, K3_SMEM);
    cudaFuncSetAttribute(k4_mma, cudaFuncAttributeMaxDynamicSharedMemorySize, K4_SMEM);

    k0_prep<<<NCAT, 128>>>(Wx, bx, Wdt, bdt, WB, WC, A_log, Dp, ln_w, ln_b);
    k0b_prep<<<(D*S)/256, 256>>>(Wout);
    k2_mma<<<BL/128, 512, K2_SMEM>>>(x);
    k3_scan<<<Bb*32, 512, K3_SMEM>>>();
    k4_mma<<<BL/64, 256, K4_SMEM>>>(x, bout, out);
}

// round 16
// speedup vs baseline: 1.0988x; 1.0988x over previous
#include <cuda_runtime.h>
#include <cuda_bf16.h>
#include <math.h>
#include <cstdint>

#define Bb   16
#define L    4096
#define D    512
#define S    64
#define BL   (Bb*L)      // 65536
#define NCAT 256         // 4 groups of 64: [dt, B, C, xproj]

// ---------------- scratch (device globals) --------------------------------
__device__ float          g_c0[NCAT];
__device__ float          g_c1[NCAT];
__device__ float          g_A[S];
__device__ float          g_Ds[D];
__device__ int            g_DsNZ;          // 1 if any clip(Dp) != 0
__device__ __nv_bfloat16  g_Whi[NCAT*D];
__device__ __nv_bfloat16  g_Wlo[NCAT*D];
__device__ __nv_bfloat16  g_Wouthi[D*S];
__device__ __nv_bfloat16  g_Woutlo[D*S];
__device__ float          g_Ac[Bb*S*L];
__device__ float          g_BX[Bb*S*L];
__device__ float          g_Cc[Bb*S*L];
// ys in s-pair-interleaved words: [b][sp=s/2][l]
__device__ uint32_t       g_ys2h[Bb*(S/2)*L];
__device__ uint32_t       g_ys2l[Bb*(S/2)*L];

// ---------------- helpers (all plain sm_80+ PTX) --------------------------
__device__ __forceinline__ uint32_t smem_u32(const void* p) {
    uint32_t a;
    asm("{ .reg .u64 t; cvta.to.shared.u64 t, %1; cvt.u32.u64 %0, t; }"
        : "=r"(a) : "l"(p));
    return a;
}
__device__ __forceinline__ void mma_bf16(float* c, const uint32_t* a, const uint32_t* b) {
    asm volatile(
        "mma.sync.aligned.m16n8k16.row.col.f32.bf16.bf16.f32 "
        "{%0,%1,%2,%3}, {%4,%5,%6,%7}, {%8,%9}, {%0,%1,%2,%3};"
        : "+f"(c[0]), "+f"(c[1]), "+f"(c[2]), "+f"(c[3])
        : "r"(a[0]), "r"(a[1]), "r"(a[2]), "r"(a[3]), "r"(b[0]), "r"(b[1]));
}
__device__ __forceinline__ void cp16(uint32_t saddr, const void* g) {
    asm volatile("cp.async.cg.shared.global [%0], [%1], 16;" :: "r"(saddr), "l"(g));
}
#define CP_COMMIT() asm volatile("cp.async.commit_group;")
#define CP_WAIT0()  asm volatile("cp.async.wait_group 0;" ::: "memory")
#define CP_WAIT1()  asm volatile("cp.async.wait_group 1;" ::: "memory")

__device__ __forceinline__ uint32_t pkbf(__nv_bfloat16 a, __nv_bfloat16 b) {
    __nv_bfloat162 t(a, b);
    return *reinterpret_cast<uint32_t*>(&t);
}

// ---------------- K0: weight prep (fold ln_w, bf16 split, PERMUTED) -------
__global__ void k0_prep(const float* __restrict__ Wx, const float* __restrict__ bx,
                        const float* __restrict__ Wdt, const float* __restrict__ bdt,
                        const float* __restrict__ WB, const float* __restrict__ WC,
                        const float* __restrict__ A_log, const float* __restrict__ Dp,
                        const float* __restrict__ ln_w, const float* __restrict__ ln_b) {
    int scat = blockIdx.x;            // 0..255 = output row n
    int g = scat >> 6, s = scat & 63;
    const float* W = (g == 0) ? Wdt : (g == 1) ? WB : (g == 2) ? WC : Wx;
    float bias = (g == 0) ? bdt[s] : (g == 3) ? bx[s] : 0.f;
    int tid = threadIdx.x;            // 128
    int n = scat;
    float c1p = 0.f, c0p = 0.f;
    for (int dp = tid; dp < D/2; dp += 128) {
        int d0 = dp * 2;
        float w0 = W[s*D + d0],     w1 = W[s*D + d0 + 1];
        float wp0 = w0 * ln_w[d0],  wp1 = w1 * ln_w[d0 + 1];
        __nv_bfloat16 h0 = __float2bfloat16_rn(wp0);
        __nv_bfloat16 h1 = __float2bfloat16_rn(wp1);
        __nv_bfloat16 l0 = __float2bfloat16_rn(wp0 - __bfloat162float(h0));
        __nv_bfloat16 l1 = __float2bfloat16_rn(wp1 - __bfloat162float(h1));
        int chunk = d0 >> 4, wc = (d0 & 15) >> 1;
        size_t off = (size_t)chunk*8192 + (size_t)(n >> 3)*256
                   + (size_t)((n & 7)*4 + (wc & 3))*8 + (size_t)(wc >> 2)*4;
        *(uint32_t*)((char*)g_Whi + off) = pkbf(h0, h1);
        *(uint32_t*)((char*)g_Wlo + off) = pkbf(l0, l1);
        c1p += wp0 + wp1;
        c0p += w0 * ln_b[d0] + w1 * ln_b[d0 + 1];
    }
    __shared__ float r1[128], r0[128];
    r1[tid] = c1p; r0[tid] = c0p; __syncthreads();
    for (int o = 64; o > 0; o >>= 1) {
        if (tid < o) { r1[tid] += r1[tid+o]; r0[tid] += r0[tid+o]; }
        __syncthreads();
    }
    if (tid == 0) { g_c1[scat] = r1[0]; g_c0[scat] = r0[0] + bias; }
    if (scat == 0 && tid < S) g_A[tid] = -expf(A_log[tid]);
    if (scat == 1) {
        int nz = 0;
        for (int d = tid; d < D; d += 128) {
            float ds = fminf(fmaxf(Dp[d], -2.f), 2.f);
            g_Ds[d] = ds;
            if (ds != 0.f) nz = 1;
        }
        __shared__ int anynz[128];
        anynz[tid] = nz; __syncthreads();
        for (int o = 64; o > 0; o >>= 1) {
            if (tid < o) anynz[tid] |= anynz[tid + o];
            __syncthreads();
        }
        if (tid == 0) g_DsNZ = anynz[0];
    }
}

// ---------------- K0b: Wout bf16 split ------------------------------------
__global__ void k0b_prep(const float* __restrict__ Wout) {
    int i = blockIdx.x * 256 + threadIdx.x;   // D*S = 32768
    float w = Wout[i];
    __nv_bfloat16 hi = __float2bfloat16_rn(w);
    g_Wouthi[i] = hi;
    g_Woutlo[i] = __float2bfloat16_rn(w - __bfloat162float(hi));
}

// ---------------- K2: HMMA bf16-split LN + projection + SSM epilogue ------
// K-chunk 32 (16 iterations), double-buffered. (R13/R14 mainloop — frozen)
#define OFF_STATS 0
#define OFF_C1    1024
#define OFF_C0    2048
#define OFF_SA    3072
#define K2_BUF0   3584
#define O2_AL     8192
#define O2_BH     16384
#define O2_BL     32768
#define K2_BUFSZ  49152
#define OFF_V     3584
#define VSTRIDE   136
#define K2_SMEM   (OFF_V + 256*VSTRIDE*4)   // 142848

__global__ void __launch_bounds__(512, 1) k2_mma(const float* __restrict__ x) {
    extern __shared__ __align__(16) char sm[];
    const uint32_t sb = smem_u32(sm);
    const int tid = threadIdx.x, lane = tid & 31, w = tid >> 5;   // w: 0..15
    const int row0 = blockIdx.x * 128;

    if (tid < 256) {
        ((float*)(sm + OFF_C1))[tid] = g_c1[tid];
        ((float*)(sm + OFF_C0))[tid] = g_c0[tid];
    }
    if (tid < 64) ((float*)(sm + OFF_SA))[tid] = g_A[tid];

    const int m0 = 64 * (w & 1);
    const int n0 = 32 * (w >> 1);
    const int mt0 = m0 >> 4;
    const int nb0 = n0 >> 3;

    float acc[4][4][4];
#pragma unroll
    for (int a = 0; a < 4; a++)
#pragma unroll
        for (int b = 0; b < 4; b++)
#pragma unroll
            for (int c = 0; c < 4; c++) acc[a][b][c] = 0.f;

    float xs = 0.f, xss = 0.f;
    float4 ax[2];
    auto loadA = [&](int ks) {
        int r = tid >> 2, q4 = tid & 3;
#pragma unroll
        for (int h = 0; h < 2; h++)
            ax[h] = *(const float4*)(x + (size_t)(row0 + r)*D + ks*32 + h*16 + q4*4);
    };
    auto storeA = [&](int bufo) {
        int r = tid >> 2, q4 = tid & 3;
        int mt = r >> 4, rr = r & 15;
#pragma unroll
        for (int h = 0; h < 2; h++) {
            float v[4] = {ax[h].x, ax[h].y, ax[h].z, ax[h].w};
            xs  += v[0] + v[1] + v[2] + v[3];
            xss += v[0]*v[0] + v[1]*v[1] + v[2]*v[2] + v[3]*v[3];
            __nv_bfloat16 hh[4], ll[4];
#pragma unroll
            for (int e = 0; e < 4; e++) {
                hh[e] = __float2bfloat16_rn(v[e]);
                ll[e] = __float2bfloat16_rn(v[e] - __bfloat162float(hh[e]));
            }
            uint32_t wH[2] = {pkbf(hh[0], hh[1]), pkbf(hh[2], hh[3])};
            uint32_t wL[2] = {pkbf(ll[0], ll[1]), pkbf(ll[2], ll[3])};
#pragma unroll
            for (int j = 0; j < 2; j++) {
                int wc = 2*q4 + j;
                int base = bufo + h*4096 + mt*512 + ((rr & 7)*4 + (wc & 3))*16
                         + ((rr >> 3) + ((wc >> 2) << 1))*4;
                *(uint32_t*)(sm + base)          = wH[j];
                *(uint32_t*)(sm + base + O2_AL)  = wL[j];
            }
        }
    };
    auto cpB = [&](int ks, int bufo) {
#pragma unroll
        for (int h = 0; h < 2; h++) {
            const char* gh = (const char*)g_Whi + (size_t)(ks*2 + h)*8192 + tid*16;
            const char* gl = (const char*)g_Wlo + (size_t)(ks*2 + h)*8192 + tid*16;
            cp16(sb + bufo + O2_BH + h*8192 + tid*16, gh);
            cp16(sb + bufo + O2_BL + h*8192 + tid*16, gl);
        }
    };
    auto compute = [&](int bufo, int h) {
        uint32_t bH[4][2], bL[4][2];
#pragma unroll
        for (int nt = 0; nt < 4; nt++) {
            int boff = bufo + O2_BH + h*8192 + (nb0 + nt)*256 + lane*8;
            uint2 th = *(const uint2*)(sm + boff);
            uint2 tl = *(const uint2*)(sm + boff + 16384);
            bH[nt][0] = th.x; bH[nt][1] = th.y;
            bL[nt][0] = tl.x; bL[nt][1] = tl.y;
        }
#pragma unroll
        for (int mt = 0; mt < 4; mt++) {
            int aoff = bufo + h*4096 + (mt0 + mt)*512 + lane*16;
            uint4 tH = *(const uint4*)(sm + aoff);
            uint4 tL = *(const uint4*)(sm + aoff + O2_AL);
            uint32_t aH[4] = {tH.x, tH.y, tH.z, tH.w};
            uint32_t aL[4] = {tL.x, tL.y, tL.z, tL.w};
#pragma unroll
            for (int nt = 0; nt < 4; nt++) mma_bf16(acc[mt][nt], aH, bH[nt]);
#pragma unroll
            for (int nt = 0; nt < 4; nt++) mma_bf16(acc[mt][nt], aL, bH[nt]);
#pragma unroll
            for (int nt = 0; nt < 4; nt++) mma_bf16(acc[mt][nt], aH, bL[nt]);
        }
    };

    loadA(0); cpB(0, K2_BUF0); CP_COMMIT();
    storeA(K2_BUF0);
    CP_WAIT0();
    __syncthreads();
    for (int s = 0; s < 16; s++) {
        int cb = K2_BUF0 + (s & 1) * K2_BUFSZ;
        int nb = K2_BUF0 + ((s + 1) & 1) * K2_BUFSZ;
        if (s < 15) { loadA(s + 1); cpB(s + 1, nb); CP_COMMIT(); }
        compute(cb, 0);
        compute(cb, 1);
        if (s < 15) storeA(nb);
        CP_WAIT0();
        __syncthreads();
    }

    // ---- fused LN stats: quad reduction ----
    xs  += __shfl_xor_sync(0xffffffffu, xs, 1);
    xs  += __shfl_xor_sync(0xffffffffu, xs, 2);
    xss += __shfl_xor_sync(0xffffffffu, xss, 1);
    xss += __shfl_xor_sync(0xffffffffu, xss, 2);
    if ((tid & 3) == 0) {
        int r = tid >> 2;
        float mu  = xs * (1.f / D);
        float var = xss * (1.f / D) - mu * mu;
        *(float2*)(sm + OFF_STATS + r*8) = make_float2(mu, rsqrtf(var + 1e-5f));
    }
    __syncthreads();

    // ---- phase 1: LN-fold, scatter v into SMEM V[col][row] ----
    float* V = (float*)(sm + OFF_V);
#pragma unroll
    for (int mt = 0; mt < 4; mt++) {
        int r_ = m0 + mt*16 + (lane >> 2);
        float2 st0 = *(const float2*)(sm + OFF_STATS + r_*8);
        float2 st1 = *(const float2*)(sm + OFF_STATS + (r_+8)*8);
#pragma unroll
        for (int nt = 0; nt < 4; nt++) {
            int c_ = n0 + nt*8 + 2*(lane & 3);
            float c1a = ((const float*)(sm + OFF_C1))[c_];
            float c1b = ((const float*)(sm + OFF_C1))[c_ + 1];
            float c0a = ((const float*)(sm + OFF_C0))[c_];
            float c0b = ((const float*)(sm + OFF_C0))[c_ + 1];
            V[c_*VSTRIDE + r_]         = st0.y*(acc[mt][nt][0] - st0.x*c1a) + c0a;
            V[(c_+1)*VSTRIDE + r_]     = st0.y*(acc[mt][nt][1] - st0.x*c1b) + c0b;
            V[c_*VSTRIDE + r_ + 8]     = st1.y*(acc[mt][nt][2] - st1.x*c1a) + c0a;
            V[(c_+1)*VSTRIDE + r_ + 8] = st1.y*(acc[mt][nt][3] - st1.x*c1b) + c0b;
        }
    }
    __syncthreads();

    // ---- phase 2: softplus/exp math, write (B,S,L) scan operands ----
    int s_ = tid & 63, rb = tid >> 6;
    float Aval = ((const float*)(sm + OFF_SA))[s_];
    int bidx = row0 >> 12;
    int l0 = row0 & (L - 1);
    size_t ob = ((size_t)(bidx*S + s_))*L + l0 + rb*16;
#pragma unroll
    for (int t4 = 0; t4 < 4; t4++) {
        int row = rb*16 + t4*4;
        float4 v0 = *(const float4*)(V + (0*64 + s_)*VSTRIDE + row);
        float4 v1 = *(const float4*)(V + (1*64 + s_)*VSTRIDE + row);
        float4 v2 = *(const float4*)(V + (2*64 + s_)*VSTRIDE + row);
        float4 v3 = *(const float4*)(V + (3*64 + s_)*VSTRIDE + row);
        float oa[4], obx[4], oc[4];
        float z0[4] = {v0.x, v0.y, v0.z, v0.w};
        float zb[4] = {v1.x, v1.y, v1.z, v1.w};
        float zc[4] = {v2.x, v2.y, v2.z, v2.w};
        float zx[4] = {v3.x, v3.y, v3.z, v3.w};
#pragma unroll
        for (int e = 0; e < 4; e++) {
            float z = z0[e];
            float sp = fmaxf(z, 0.f) + log1pf(expf(-fabsf(z)));
            float delta = sp * 0.01f + 1e-4f;
            float dA = fminf(fmaxf(delta * Aval, -10.f), -1e-4f);
            float ad = expf(dA);
            oa[e]  = fminf(fmaxf(ad, 0.001f), 0.999f) + 1e-10f;
            obx[e] = delta * zb[e] * zx[e];
            oc[e]  = zc[e];
        }
        *(float4*)(g_Ac + ob + t4*4) = make_float4(oa[0], oa[1], oa[2], oa[3]);
        *(float4*)(g_BX + ob + t4*4) = make_float4(obx[0], obx[1], obx[2], obx[3]);
        *(float4*)(g_Cc + ob + t4*4) = make_float4(oc[0], oc[1], oc[2], oc[3]);
    }
}

// ---------------- K3: affine scan; split-group staging (C overlapped) -----
#define K3_HALF 20480
#define K3_SA   0
#define K3_SB   (2*K3_HALF)
#define K3_SC   (4*K3_HALF)
#define K3_SMEM (6*K3_HALF)           // 122880
__global__ void __launch_bounds__(512, 1) k3_scan() {
    extern __shared__ __align__(16) char sm[];
    const uint32_t sb = smem_u32(sm);
    int tid = threadIdx.x;
    int h = tid >> 8, t = tid & 255;
    int lane = tid & 31, w = tid >> 5;
    int b = blockIdx.x >> 5, sp = blockIdx.x & 31;

    // group 0: A + B (needed first)
#pragma unroll
    for (int i = 0; i < 4; i++) {
        int c = tid + 512*i;
        int h2 = c >> 10, cc = c & 1023;
        int s2 = sp*2 + h2;
        size_t gbase = ((size_t)(b*S + s2))*L + cc*4;
        uint32_t dst = h2*K3_HALF + (cc >> 2)*80 + (cc & 3)*16;
        cp16(sb + K3_SA + dst, g_Ac + gbase);
        cp16(sb + K3_SB + dst, g_BX + gbase);
    }
    CP_COMMIT();
    // group 1: C (needed only after the scan)
#pragma unroll
    for (int i = 0; i < 4; i++) {
        int c = tid + 512*i;
        int h2 = c >> 10, cc = c & 1023;
        int s2 = sp*2 + h2;
        size_t gbase = ((size_t)(b*S + s2))*L + cc*4;
        uint32_t dst = h2*K3_HALF + (cc >> 2)*80 + (cc & 3)*16;
        cp16(sb + K3_SC + dst, g_Cc + gbase);
    }
    CP_COMMIT();
    CP_WAIT1();          // A+B landed; C may still be in flight
    __syncthreads();

    const char* gbase_ = sm + h*K3_HALF + t*80;
    float a[16], bxv[16];
#pragma unroll
    for (int q = 0; q < 4; q++) {
        *(float4*)(a + q*4)   = *(const float4*)(gbase_ + K3_SA + q*16);
        *(float4*)(bxv + q*4) = *(const float4*)(gbase_ + K3_SB + q*16);
    }

    float P = 1.f, Q = 0.f;
#pragma unroll
    for (int i = 0; i < 16; i++) { Q = a[i] * (Q + bxv[i]); P *= a[i]; }

#pragma unroll
    for (int d = 1; d < 32; d <<= 1) {
        float Pp = __shfl_up_sync(0xffffffffu, P, d);
        float Qp = __shfl_up_sync(0xffffffffu, Q, d);
        if (lane >= d) { Q = P * Qp + Q; P = P * Pp; }
    }
    __shared__ float wP[16], wQ[16];
    if (lane == 31) { wP[w] = P; wQ[w] = Q; }
    CP_WAIT0();          // C landed (per-thread); barrier below publishes it
    __syncthreads();
    float Qw = 0.f;
    for (int w_ = h*8; w_ < w; w_++) { Qw = wP[w_] * Qw + wQ[w_]; }
    float P2 = __shfl_up_sync(0xffffffffu, P, 1);
    float Q2 = __shfl_up_sync(0xffffffffu, Q, 1);
    float hh = (lane == 0) ? Qw : (P2 * Qw + Q2);

    float y[16];
#pragma unroll
    for (int q = 0; q < 4; q++) {
        float4 cv = *(const float4*)(gbase_ + K3_SC + q*16);
        float c4[4] = {cv.x, cv.y, cv.z, cv.w};
#pragma unroll
        for (int e = 0; e < 4; e++) {
            int i = q*4 + e;
            hh = a[i] * (hh + bxv[i]);
            y[i] = c4[e] * hh;
        }
    }

    float* sy = (float*)(sm + K3_SA);
    __syncthreads();
    if (h == 1) {
#pragma unroll
        for (int i = 0; i < 16; i++) sy[t*17 + i] = y[i];
    }
    __syncthreads();
    if (h == 0) {
        uint32_t whi[16], wlo[16];
#pragma unroll
        for (int i = 0; i < 16; i++) {
            float ye = y[i];
            float yo = sy[t*17 + i];
            __nv_bfloat16 he = __float2bfloat16_rn(ye);
            __nv_bfloat16 ho = __float2bfloat16_rn(yo);
            __nv_bfloat16 le = __float2bfloat16_rn(ye - __bfloat162float(he));
            __nv_bfloat16 lo = __float2bfloat16_rn(yo - __bfloat162float(ho));
            whi[i] = pkbf(he, ho);
            wlo[i] = pkbf(le, lo);
        }
        size_t off = ((size_t)(b*32 + sp))*L + t*16;
#pragma unroll
        for (int q = 0; q < 4; q++) {
            *(uint4*)(g_ys2h + off + q*4) = make_uint4(whi[q*4], whi[q*4+1], whi[q*4+2], whi[q*4+3]);
            *(uint4*)(g_ys2l + off + q*4) = make_uint4(wlo[q*4], wlo[q*4+1], wlo[q*4+2], wlo[q*4+3]);
        }
    }
}

// ---------------- K4: out = ys @ Wout^T + bout [+ clip(Dp)*x] (HMMA) ------
#define K4_AH   0
#define K4_AL   9216
#define K4_B0   18432
#define K4_B1   55296
#define K4_BLO  18432
#define K4_SMEM 92160
__global__ void __launch_bounds__(256, 2) k4_mma(const float* __restrict__ x,
                                                 const float* __restrict__ bout,
                                                 float* __restrict__ out) {
    extern __shared__ __align__(16) char sm[];
    const uint32_t sb = smem_u32(sm);
    const int tid = threadIdx.x, lane = tid & 31, w = tid >> 5;
    const int row0 = blockIdx.x * 64;
    const int bidx = row0 >> 12;
    const int l0   = row0 & (L - 1);
    const int dsnz = g_DsNZ;

    auto cpB = [&](int d0, uint32_t bufo) {
#pragma unroll
        for (int i = 0; i < 4; i++) {
            int li = tid*4 + i;
            int n = li >> 3, q = li & 7;
            uint32_t dst = bufo + n*144 + q*16;
            cp16(sb + dst,          g_Wouthi + (size_t)(d0 + n)*S + q*8);
            cp16(sb + dst + K4_BLO, g_Woutlo + (size_t)(d0 + n)*S + q*8);
        }
    };

#pragma unroll
    for (int i = 0; i < 2; i++) {
        int chunk = tid + 256*i;
        int sp = chunk >> 4, lq = chunk & 15;
        size_t g = ((size_t)(bidx*32 + sp))*L + l0 + lq*4;
        uint32_t dsto = (uint32_t)(sp*72 + lq*4) * 4u;
        cp16(sb + K4_AH + dsto, g_ys2h + g);
        cp16(sb + K4_AL + dsto, g_ys2l + g);
    }
    cpB(0, K4_B0);
    CP_COMMIT();
    CP_WAIT0();
    __syncthreads();

    const int m0 = 32 * (w & 1);
    const int n0 = 32 * (w >> 1);

    for (int dt = 0; dt < 4; dt++) {
        uint32_t bufo = (dt & 1) ? K4_B1 : K4_B0;
        if (dt < 3) { cpB((dt + 1) * 128, (dt & 1) ? K4_B0 : K4_B1); CP_COMMIT(); }
        int d0 = dt * 128;

        float acc[2][4][4];
#pragma unroll
        for (int a = 0; a < 2; a++)
#pragma unroll
            for (int b = 0; b < 4; b++)
#pragma unroll
                for (int c = 0; c < 4; c++) acc[a][b][c] = 0.f;

#pragma unroll
        for (int kk = 0; kk < 4; kk++) {
            int kp = kk*16 + 2*(lane & 3);
            uint32_t bH[4][2], bL[4][2];
#pragma unroll
            for (int nt = 0; nt < 4; nt++) {
                uint32_t boff = bufo + (n0 + nt*8 + (lane >> 2))*144 + kp*2;
                bH[nt][0] = *(const uint32_t*)(sm + boff);
                bH[nt][1] = *(const uint32_t*)(sm + boff + 16);
                bL[nt][0] = *(const uint32_t*)(sm + boff + K4_BLO);
                bL[nt][1] = *(const uint32_t*)(sm + boff + K4_BLO + 16);
            }
#pragma unroll
            for (int mt = 0; mt < 2; mt++) {
                int abase = ((kk*8 + (lane & 3))*72 + m0 + mt*16 + (lane >> 2)) * 4;
                uint32_t aH[4], aL[4];
                aH[0] = *(const uint32_t*)(sm + K4_AH + abase);
                aH[1] = *(const uint32_t*)(sm + K4_AH + abase + 32);       // l+8
                aH[2] = *(const uint32_t*)(sm + K4_AH + abase + 4*72*4);   // sp+4
                aH[3] = *(const uint32_t*)(sm + K4_AH + abase + 4*72*4 + 32);
                aL[0] = *(const uint32_t*)(sm + K4_AL + abase);
                aL[1] = *(const uint32_t*)(sm + K4_AL + abase + 32);
                aL[2] = *(const uint32_t*)(sm + K4_AL + abase + 4*72*4);
                aL[3] = *(const uint32_t*)(sm + K4_AL + abase + 4*72*4 + 32);
#pragma unroll
                for (int nt = 0; nt < 4; nt++) mma_bf16(acc[mt][nt], aH, bH[nt]);
#pragma unroll
                for (int nt = 0; nt < 4; nt++) mma_bf16(acc[mt][nt], aL, bH[nt]);
#pragma unroll
                for (int nt = 0; nt < 4; nt++) mma_bf16(acc[mt][nt], aH, bL[nt]);
            }
        }

        if (dsnz) {
#pragma unroll
            for (int nt = 0; nt < 4; nt++) {
                int cd = d0 + n0 + nt*8 + 2*(lane & 3);
                float2 bo = *(const float2*)(bout + cd);
                float2 ds = *(const float2*)(g_Ds + cd);
#pragma unroll
                for (int mt = 0; mt < 2; mt++) {
                    int r_ = row0 + m0 + mt*16 + (lane >> 2);
                    float2 xv0 = *(const float2*)(x + (size_t)r_*D + cd);
                    float2 xv1 = *(const float2*)(x + (size_t)(r_+8)*D + cd);
                    float2 o0, o1;
                    o0.x = acc[mt][nt][0] + bo.x + ds.x*xv0.x;
                    o0.y = acc[mt][nt][1] + bo.y + ds.y*xv0.y;
                    o1.x = acc[mt][nt][2] + bo.x + ds.x*xv1.x;
                    o1.y = acc[mt][nt][3] + bo.y + ds.y*xv1.y;
                    *(float2*)(out + (size_t)r_*D + cd)     = o0;
                    *(float2*)(out + (size_t)(r_+8)*D + cd) = o1;
                }
            }
        } else {
#pragma unroll
            for (int nt = 0; nt < 4; nt++) {
                int cd = d0 + n0 + nt*8 + 2*(lane & 3);
                float2 bo = *(const float2*)(bout + cd);
#pragma unroll
                for (int mt = 0; mt < 2; mt++) {
                    int r_ = row0 + m0 + mt*16 + (lane >> 2);
                    float2 o0, o1;
                    o0.x = acc[mt][nt][0] + bo.x;
                    o0.y = acc[mt][nt][1] + bo.y;
                    o1.x = acc[mt][nt][2] + bo.x;
                    o1.y = acc[mt][nt][3] + bo.y;
                    *(float2*)(out + (size_t)r_*D + cd)     = o0;
                    *(float2*)(out + (size_t)(r_+8)*D + cd) = o1;
                }
            }
        }

        if (dt < 3) CP_WAIT0();
        __syncthreads();
    }
}

// ---------------- launch --------------------------------------------------
extern "C" void kernel_launch(void* const* d_in, const int* in_sizes, int n_in,
                              void* d_out, int out_size) {
    const float* x     = (const float*)d_in[0];
    const float* ln_w  = (const float*)d_in[1];
    const float* ln_b  = (const float*)d_in[2];
    const float* Wx    = (const float*)d_in[3];
    const float* bx    = (const float*)d_in[4];
    const float* Wdt   = (const float*)d_in[5];
    const float* bdt   = (const float*)d_in[6];
    const float* A_log = (const float*)d_in[7];
    const float* WB    = (const float*)d_in[8];
    const float* WC    = (const float*)d_in[9];
    const float* Dp    = (const float*)d_in[10];
    const float* Wout  = (const float*)d_in[11];
    const float* bout  = (const float*)d_in[12];
    float* out = (float*)d_out;

    cudaFuncSetAttribute(k2_mma, cudaFuncAttributeMaxDynamicSharedMemorySize, K2_SMEM);
    cudaFuncSetAttribute(k3_scan, cudaFuncAttributeMaxDynamicSharedMemorySize, K3_SMEM);
    cudaFuncSetAttribute(k4_mma, cudaFuncAttributeMaxDynamicSharedMemorySize, K4_SMEM);

    k0_prep<<<NCAT, 128>>>(Wx, bx, Wdt, bdt, WB, WC, A_log, Dp, ln_w, ln_b);
    k0b_prep<<<(D*S)/256, 256>>>(Wout);
    k2_mma<<<BL/128, 512, K2_SMEM>>>(x);
    k3_scan<<<Bb*32, 512, K3_SMEM>>>();
    k4_mma<<<BL/64, 256, K4_SMEM>>>(x, bout, out);
}